// round 17
// baseline (speedup 1.0000x reference)
#include <cuda_runtime.h>
#include <cuda_fp16.h>
#include <cstdint>

#define LN_EPS 1e-5f

static constexpr int Fdim = 64;
static constexpr int Hdim = 128;
static constexpr int SLABP = 129;   // slab row pitch (words): ~conflict-free lanes

// cross-CTA combine scratch (written every launch before read; counter self-resets)
__device__ int d_partial[1024][128];
__device__ int d_counter[512];

// pack two floats as fp16x2: lo -> low half, hi -> high half
__device__ __forceinline__ uint32_t packh(float lo, float hi) {
    uint32_t r;
    asm("cvt.rn.f16x2.f32 %0, %1, %2;" : "=r"(r) : "f"(hi), "f"(lo));
    return r;
}

__device__ __forceinline__ void mma_f16(float c[4], const uint32_t a[4], const uint32_t b[2]) {
    asm volatile(
        "mma.sync.aligned.m16n8k16.row.col.f32.f16.f16.f32 "
        "{%0,%1,%2,%3}, {%4,%5,%6,%7}, {%8,%9}, {%0,%1,%2,%3};\n"
        : "+f"(c[0]), "+f"(c[1]), "+f"(c[2]), "+f"(c[3])
        : "r"(a[0]), "r"(a[1]), "r"(a[2]), "r"(a[3]), "r"(b[0]), "r"(b[1]));
}

// grid = 2N: CTA (n, half) owns 256 rows; 8 warps x 16 rows x 2 sweeps.
// Permuted fragment layouts: k-cols {4s..4s+3} per lane -> x rows load as
// LDG.128; n-cols interleaved across tile pairs -> y stores as STG.128 and
// params stage as float4. GEMM/LN/pool/combine structure = R15 champion.
extern "C" __global__ void __launch_bounds__(256, 2)
fused_kernel(const float* __restrict__ x, const int* __restrict__ mask,
             const float* __restrict__ W, const float* __restrict__ bias,
             const float* __restrict__ gamma, const float* __restrict__ beta,
             float* __restrict__ out, float* __restrict__ gout, int L)
{
    __shared__ uint4  Bfrag[4 * 8 * 32];    // [ks][tpair][lane] = {t0.b0,t0.b1,t1.b0,t1.b1}
    __shared__ int    gsm8[8 * SLABP];      // pooled max slab (int bits of floats >= 0)
    __shared__ int    gsm[128];
    __shared__ float4 cg4[8][4];            // gamma[16u+4s .. +3]
    __shared__ float4 ct4[8][4];            // beta  float4 (permuted)
    __shared__ float4 cb4[8][4];            // bias  float4 (permuted)
    __shared__ int    sIsLast;

    const int tid  = threadIdx.x;
    const int bidx = blockIdx.x;
    const int n    = bidx >> 1;
    const int half = bidx & 1;

    // pack W into permuted paired B-fragment order:
    // tile t -> actual h = (t>>1)*16 + 2*q + (t&1); k-slot (s,j) -> k = ks*16+4s+j
    for (int idx = tid; idx < 4 * 8 * 32; idx += 256) {
        int lane = idx & 31;
        int tp   = (idx >> 5) & 7;
        int ks   = idx >> 8;
        int q = lane >> 2, s = lane & 3;
        int kb = ks * 16 + 4 * s;
        int h0 = tp * 16 + 2 * q;        // tile 2tp
        int h1 = h0 + 1;                 // tile 2tp+1
        float4 w0 = *reinterpret_cast<const float4*>(W + h0 * Fdim + kb);
        float4 w1 = *reinterpret_cast<const float4*>(W + h1 * Fdim + kb);
        uint4 v;
        v.x = packh(w0.x, w0.y);   // tile 2tp,   b0 (k0,k1)
        v.y = packh(w0.z, w0.w);   // tile 2tp,   b1 (k2,k3)
        v.z = packh(w1.x, w1.y);   // tile 2tp+1, b0
        v.w = packh(w1.z, w1.w);   // tile 2tp+1, b1
        Bfrag[idx] = v;
    }
    // stage permuted params: entry (u, s) covers actual cols 16u+4s .. +3
    if (tid < 32) {
        int u = tid >> 2, s = tid & 3;
        int col = u * 16 + 4 * s;
        cg4[u][s] = *reinterpret_cast<const float4*>(gamma + col);
        ct4[u][s] = *reinterpret_cast<const float4*>(beta  + col);
        cb4[u][s] = *reinterpret_cast<const float4*>(bias  + col);
    }
    for (int i = tid; i < 8 * SLABP; i += 256) gsm8[i] = 0;
    __syncthreads();

    const int lane = tid & 31;
    const int warp = tid >> 5;
    const int q = lane >> 2, s = lane & 3;
    int* slab = gsm8 + q * SLABP;

    const int rbeg = half * 256;
    for (int rb = rbeg + warp * 16; rb < rbeg + 256; rb += 128) {
        const size_t rowA = (size_t)n * L + rb + q;
        const size_t rowB = rowA + 8;
        const float* xA = x + rowA * Fdim;
        const float* xB = x + rowB * Fdim;

        // acc initialized with (permuted) bias
        float acc[16][4];
        #pragma unroll
        for (int u = 0; u < 8; u++) {
            float4 b4 = cb4[u][s];
            acc[2 * u][0]     = b4.x; acc[2 * u][1]     = b4.z;
            acc[2 * u][2]     = b4.x; acc[2 * u][3]     = b4.z;
            acc[2 * u + 1][0] = b4.y; acc[2 * u + 1][1] = b4.w;
            acc[2 * u + 1][2] = b4.y; acc[2 * u + 1][3] = b4.w;
        }

        #pragma unroll
        for (int ks = 0; ks < 4; ks++) {
            const int kb = ks * 16 + 4 * s;
            float4 XA = *reinterpret_cast<const float4*>(xA + kb);   // one LDG.128
            float4 XB = *reinterpret_cast<const float4*>(xB + kb);
            uint32_t ah[4] = { packh(XA.x, XA.y), packh(XB.x, XB.y),
                               packh(XA.z, XA.w), packh(XB.z, XB.w) };
            const uint4* Bp = Bfrag + ks * 256 + lane;
            #pragma unroll
            for (int tp = 0; tp < 8; tp++) {
                uint4 bv = Bp[tp * 32];
                uint32_t bh0[2] = { bv.x, bv.y };
                uint32_t bh1[2] = { bv.z, bv.w };
                mma_f16(acc[2 * tp],     ah, bh0);
                mma_f16(acc[2 * tp + 1], ah, bh1);
            }
        }

        float sumA = 0.f, sqA = 0.f, sumB = 0.f, sqB = 0.f;
        #pragma unroll
        for (int t = 0; t < 16; t++) {
            sumA += acc[t][0] + acc[t][1];
            sqA  += acc[t][0] * acc[t][0] + acc[t][1] * acc[t][1];
            sumB += acc[t][2] + acc[t][3];
            sqB  += acc[t][2] * acc[t][2] + acc[t][3] * acc[t][3];
        }
        #pragma unroll
        for (int m = 1; m <= 2; m <<= 1) {
            sumA += __shfl_xor_sync(0xffffffffu, sumA, m);
            sqA  += __shfl_xor_sync(0xffffffffu, sqA, m);
            sumB += __shfl_xor_sync(0xffffffffu, sumB, m);
            sqB  += __shfl_xor_sync(0xffffffffu, sqB, m);
        }
        const float inv = 1.0f / (float)Hdim;
        float muA = sumA * inv, muB = sumB * inv;
        float rsA = rsqrtf(fmaxf(sqA * inv - muA * muA, 0.f) + LN_EPS);
        float rsB = rsqrtf(fmaxf(sqB * inv - muB * muB, 0.f) + LN_EPS);

        const bool mA = (mask[rowA] != 0);
        const bool mB = (mask[rowB] != 0);
        float* outA = out + rowA * (2 * Hdim);
        float* outB = out + rowB * (2 * Hdim);

        #pragma unroll
        for (int u = 0; u < 8; u++) {
            const int col = u * 16 + 4 * s;
            float4 g4 = cg4[u][s];
            float4 t4 = ct4[u][s];
            // A-row (q): fragment -> actual col order {2u.c0, 2u+1.c0, 2u.c1, 2u+1.c1}
            float4 yA, yB;
            yA.x = fmaxf((acc[2*u][0]   - muA) * rsA * g4.x + t4.x, 0.f);
            yA.y = fmaxf((acc[2*u+1][0] - muA) * rsA * g4.y + t4.y, 0.f);
            yA.z = fmaxf((acc[2*u][1]   - muA) * rsA * g4.z + t4.z, 0.f);
            yA.w = fmaxf((acc[2*u+1][1] - muA) * rsA * g4.w + t4.w, 0.f);
            yB.x = fmaxf((acc[2*u][2]   - muB) * rsB * g4.x + t4.x, 0.f);
            yB.y = fmaxf((acc[2*u+1][2] - muB) * rsB * g4.y + t4.y, 0.f);
            yB.z = fmaxf((acc[2*u][3]   - muB) * rsB * g4.z + t4.z, 0.f);
            yB.w = fmaxf((acc[2*u+1][3] - muB) * rsB * g4.w + t4.w, 0.f);
            *reinterpret_cast<float4*>(outA + col) = yA;     // one STG.128
            *reinterpret_cast<float4*>(outB + col) = yB;
            float p0 = fmaxf(mA ? yA.x : 0.f, mB ? yB.x : 0.f);
            float p1 = fmaxf(mA ? yA.y : 0.f, mB ? yB.y : 0.f);
            float p2 = fmaxf(mA ? yA.z : 0.f, mB ? yB.z : 0.f);
            float p3 = fmaxf(mA ? yA.w : 0.f, mB ? yB.w : 0.f);
            atomicMax(slab + col,     __float_as_int(p0));
            atomicMax(slab + col + 1, __float_as_int(p1));
            atomicMax(slab + col + 2, __float_as_int(p2));
            atomicMax(slab + col + 3, __float_as_int(p3));
        }
    }
    __syncthreads();

    // fold the 8 q-rows of the slab -> per-CTA partial; publish
    if (tid < 128) {
        int m = gsm8[tid];
        #pragma unroll
        for (int k = 1; k < 8; k++) m = max(m, gsm8[k * SLABP + tid]);
        d_partial[bidx][tid] = m;
    }
    __threadfence();
    __syncthreads();
    if (tid == 0) sIsLast = (atomicAdd(&d_counter[n], 1) == 1);
    __syncthreads();
    if (!sIsLast) return;

    __threadfence();
    if (tid < 128) {
        const int base = n << 1;
        int c = max(d_partial[base][tid], d_partial[base + 1][tid]);
        gsm[tid] = c;
        gout[(size_t)n * Hdim + tid] = __int_as_float(c);
    }
    if (tid == 0) d_counter[n] = 0;   // self-reset for next graph replay
    __syncthreads();

    // broadcast g into out[n, :, H:2H] (whole batch, 8 warps)
    float4 gv;
    gv.x = __int_as_float(gsm[lane * 4 + 0]);
    gv.y = __int_as_float(gsm[lane * 4 + 1]);
    gv.z = __int_as_float(gsm[lane * 4 + 2]);
    gv.w = __int_as_float(gsm[lane * 4 + 3]);
    float* obase = out + (size_t)n * L * (2 * Hdim) + Hdim;
    for (int r = warp; r < L; r += 8)
        *reinterpret_cast<float4*>(obase + (size_t)r * (2 * Hdim) + lane * 4) = gv;
}

extern "C" void kernel_launch(void* const* d_in, const int* in_sizes, int n_in,
                              void* d_out, int out_size) {
    const float* x     = (const float*)d_in[0];
    const int*   mask  = (const int*)d_in[1];
    const float* W     = (const float*)d_in[2];
    const float* bias  = (const float*)d_in[3];
    const float* gamma = (const float*)d_in[4];
    const float* beta  = (const float*)d_in[5];
    float* out = (float*)d_out;

    const int NL = in_sizes[1];
    const long long ysize = (long long)NL * 2 * Hdim;
    const int N = (int)(((long long)out_size - ysize) / Hdim);
    const int L = NL / N;
    float* g = out + ysize;

    fused_kernel<<<2 * N, 256>>>(x, mask, W, bias, gamma, beta, out, g, L);
}